// round 8
// baseline (speedup 1.0000x reference)
#include <cuda_runtime.h>

// Screen geometry (must match reference exactly, as float32)
#define NX 1024
#define NY 1024
__device__ __constant__ float c_LEFT   = -0.00512f;
__device__ __constant__ float c_RIGHT  =  0.00512f;
__device__ __constant__ float c_BOTTOM = -0.00512f;
__device__ __constant__ float c_TOP    =  0.00512f;
__device__ __constant__ float c_HSTEP  =  1e-5f;
__device__ __constant__ float c_VSTEP  =  1e-5f;

#define N_PARTICLES 16777216
#define N_F4   (N_PARTICLES / 4)     // 4,194,304 float4s
#define TPB    256
#define GRID   1024                  // 22 regs, 0 smem -> 8 CTA/SM capacity;
                                     // 148*8=1184 >= 1024 -> single wave, co-resident
#define ITERS  (N_F4 / (GRID * TPB)) // 16 float4s per thread
#define IMG_F4 (NX * NY / 4)         // 262,144 = GRID * TPB exactly

__device__ unsigned g_zero_arrived = 0;   // fused-zero barrier (reset each run)
__device__ unsigned g_blocks_done  = 0;   // replay-safe reset

__device__ __forceinline__ void deposit(float x, float y, float* __restrict__ out) {
    // Match jnp.floor((x - LEFT)/HSTEP) in fp32 with IEEE round-to-nearest division.
    bool valid = (x >= c_LEFT) & (x <= c_RIGHT) & (y >= c_BOTTOM) & (y <= c_TOP);
    int ix = (int)floorf(__fdiv_rn(x - c_LEFT,   c_HSTEP));
    int iy = (int)floorf(__fdiv_rn(y - c_BOTTOM, c_VSTEP));
    if (x == c_RIGHT) ix = NX - 1;
    if (y == c_TOP)   iy = NY - 1;
    ix = min(max(ix, 0), NX - 1);
    iy = min(max(iy, 0), NY - 1);
    int flat = (NY - 1 - iy) * NX + ix;
    if (valid) atomicAdd(out + flat, 1.0f);  // fire-and-forget -> RED.E.ADD.F32
}

__global__ void __launch_bounds__(TPB)
hist_fused_kernel(const float4* __restrict__ xs4, const float4* __restrict__ ys4,
                  const float* __restrict__ mis, float* __restrict__ out) {
    const int tid = threadIdx.x;
    const int bid = blockIdx.x;

    // ---- Fused zero: exactly one float4 per thread covers the 4 MB image ----
    ((float4*)out)[bid * TPB + tid] = make_float4(0.f, 0.f, 0.f, 0.f);

    // ---- Single-wave grid barrier (all 1024 CTAs provably co-resident) ----
    __syncthreads();
    if (tid == 0) {
        __threadfence();                       // make our zero-stores visible
        atomicAdd(&g_zero_arrived, 1u);
        volatile unsigned* p = &g_zero_arrived;
        while (*p < GRID) __nanosleep(64);     // backoff: keep L2 line quiet
        __threadfence();                       // acquire
    }
    __syncthreads();

    // ---- Histogram: 16 block-strided float4s (64 particles) per thread ----
    const float mx = __ldg(mis);
    const float my = __ldg(mis + 1);
    int i = bid * TPB + tid;
#pragma unroll 4
    for (int it = 0; it < ITERS; it++, i += GRID * TPB) {
        float4 x4 = xs4[i];
        float4 y4 = ys4[i];
        deposit(x4.x - mx, y4.x - my, out);
        deposit(x4.y - mx, y4.y - my, out);
        deposit(x4.z - mx, y4.z - my, out);
        deposit(x4.w - mx, y4.w - my, out);
    }

    // ---- Replay-safe reset of barrier counters (last block) ----
    __syncthreads();
    if (tid == 0) {
        __threadfence();
        unsigned d = atomicAdd(&g_blocks_done, 1u);
        if (d == GRID - 1) {
            g_zero_arrived = 0;
            g_blocks_done  = 0;
            __threadfence();
        }
    }
}

extern "C" void kernel_launch(void* const* d_in, const int* in_sizes, int n_in,
                              void* d_out, int out_size) {
    const float* xs  = (const float*)d_in[0];
    const float* ys  = (const float*)d_in[1];
    const float* mis = (const float*)d_in[2];
    float* out = (float*)d_out;

    hist_fused_kernel<<<GRID, TPB>>>((const float4*)xs, (const float4*)ys, mis, out);
}

// round 9
// speedup vs baseline: 1.6779x; 1.6779x over previous
#include <cuda_runtime.h>

// Screen geometry (must match reference exactly, as float32)
#define NX 1024
#define NY 1024
__device__ __constant__ float c_LEFT   = -0.00512f;
__device__ __constant__ float c_RIGHT  =  0.00512f;
__device__ __constant__ float c_BOTTOM = -0.00512f;
__device__ __constant__ float c_TOP    =  0.00512f;
__device__ __constant__ float c_HSTEP  =  1e-5f;
__device__ __constant__ float c_VSTEP  =  1e-5f;

#define N_PARTICLES 16777216
#define TPB 256

__global__ void zero_out_kernel(float4* __restrict__ out, int n4) {
    int i = blockIdx.x * blockDim.x + threadIdx.x;
    if (i < n4) out[i] = make_float4(0.f, 0.f, 0.f, 0.f);
}

__device__ __forceinline__ void deposit(float x, float y, float* __restrict__ out) {
    // Match jnp.floor((x - LEFT)/HSTEP) in fp32 with IEEE round-to-nearest division.
    bool valid = (x >= c_LEFT) & (x <= c_RIGHT) & (y >= c_BOTTOM) & (y <= c_TOP);
    int ix = (int)floorf(__fdiv_rn(x - c_LEFT,   c_HSTEP));
    int iy = (int)floorf(__fdiv_rn(y - c_BOTTOM, c_VSTEP));
    if (x == c_RIGHT) ix = NX - 1;
    if (y == c_TOP)   iy = NY - 1;
    ix = min(max(ix, 0), NX - 1);
    iy = min(max(iy, 0), NY - 1);
    int flat = (NY - 1 - iy) * NX + ix;
    if (valid) atomicAdd(out + flat, 1.0f);  // fire-and-forget -> RED.E.ADD.F32
}

__global__ void __launch_bounds__(TPB)
hist_kernel(const float4* __restrict__ xs4, const float4* __restrict__ ys4,
            const float* __restrict__ mis, float* __restrict__ out) {
    int i = blockIdx.x * blockDim.x + threadIdx.x;  // one float4 per thread
    float mx = __ldg(mis);
    float my = __ldg(mis + 1);
    // Streaming (evict-first) loads: the 134 MB particle stream is read once;
    // keep L2 capacity/bandwidth for the atomic RMW sector traffic.
    float4 x4 = __ldcs(&xs4[i]);
    float4 y4 = __ldcs(&ys4[i]);
    deposit(x4.x - mx, y4.x - my, out);
    deposit(x4.y - mx, y4.y - my, out);
    deposit(x4.z - mx, y4.z - my, out);
    deposit(x4.w - mx, y4.w - my, out);
}

extern "C" void kernel_launch(void* const* d_in, const int* in_sizes, int n_in,
                              void* d_out, int out_size) {
    const float* xs  = (const float*)d_in[0];
    const float* ys  = (const float*)d_in[1];
    const float* mis = (const float*)d_in[2];
    float* out = (float*)d_out;

    // 1) zero the image (out_size = NX*NY floats, divisible by 4)
    int n4 = out_size / 4;
    zero_out_kernel<<<(n4 + 255) / 256, 256>>>((float4*)out, n4);

    // 2) histogram: 16,777,216 particles, 4 per thread (champion config)
    int work = N_PARTICLES / 4;          // 4,194,304 threads
    hist_kernel<<<work / 256, 256>>>((const float4*)xs, (const float4*)ys, mis, out);
}